// round 14
// baseline (speedup 1.0000x reference)
#include <cuda_runtime.h>
#include <cuda_bf16.h>
#include <mma.h>
#include <math.h>

using namespace nvcuda;

#define CAP 192

// ---------------- static device scratch (no allocation allowed) ----------------
__device__ float g_S[(size_t)4096*4096];      // [0,16M) Gr | [16,32M) Gc | [32,48M) part | [48,56M) A1b | [56,60M) Grb | [60,64M) Gcb
__device__ float g_As1[(size_t)2048*2048];
__device__ float g_As2[(size_t)1024*1024];
__device__ float g_As3[(size_t)512*512];
__device__ float g_A4[(size_t)256*256];
__device__ float g_x0[4096*32];
__device__ float g_x1[2048*64];
__device__ float g_x2[1024*128];
__device__ float g_x3[512*256];
__device__ float g_x4[256*512];
__device__ float g_xg[2048*64];
__device__ float g_xu[4096*64];
__device__ float g_xcat[4096*64];
__device__ float g_bU[4096*64];
__device__ float g_bZ[4096*64];
__device__ __nv_bfloat16 g_Ucat[2048*192];
__device__ float g_dinv0[4096], g_fill0[4096];
__device__ float g_dinv1[2048], g_fill1[2048];
__device__ float g_dinv2[1024], g_fill2[1024];
__device__ float g_dinv3[512],  g_fill3[512];
__device__ float g_dinv4[256],  g_fill4[256];
__device__ float g_score[4096];
__device__ int   g_perm0[2048];
__device__ int   g_perm1[1024];
__device__ int   g_perm2[512];
__device__ int   g_perm3[256];
__device__ int   g_iz[4096*3];                // degi | selfc | cnt (one memset)
__device__ int   g_tcnt[4096*8];              // per-chunk partial ranks (no memset needed)
__device__ int   g_inv0[4096];
__device__ int   g_inv1[2048];
__device__ int   g_inv2[1024];
__device__ int   g_inv3[512];
__device__ int   g_bucket[4096*CAP];

// ---------------- sparse level-0 kernels ----------------

__global__ void k_edge_stats(const int* __restrict__ e, int E, int* degi, int* selfc){
    int i = blockIdx.x*blockDim.x + threadIdx.x;
    if (i >= E) return;
    int s = e[i], d = e[E+i];
    atomicAdd(&degi[d], 1);
    if (s == d) atomicAdd(&selfc[d], 1);
}

__global__ void k_deg0_fin(const int* __restrict__ degi, const int* __restrict__ selfc,
                           float* dinv, float* fill, int n){
    int i = blockIdx.x*blockDim.x + threadIdx.x;
    if (i >= n) return;
    float f = (selfc[i] == 0) ? 2.0f : 0.0f;
    float deg = (float)degi[i] + f;
    dinv[i] = (deg > 0.f) ? 1.0f/sqrtf(deg) : 0.0f;
    fill[i] = f;
}

__global__ void k_bucket_fill(const int* __restrict__ e, int E, int* cnt, int* bucket){
    int i = blockIdx.x*blockDim.x + threadIdx.x;
    if (i >= E) return;
    int s = e[i], d = e[E+i];
    if (s == d) return;
    int p = atomicAdd(&cnt[s], 1);
    if (p < CAP) bucket[s*CAP + p] = d;
}

__global__ void k_scatter_aug_inv(const int* __restrict__ e, int E, const int* __restrict__ inv,
                                  float* A, int k){
    int i = blockIdx.x*blockDim.x + threadIdx.x;
    if (i >= E) return;
    int s = e[i], d = e[E+i];
    if (s == d) return;
    int ir = inv[d], ic = inv[s];
    if (ir >= 0 && ic >= 0) atomicAdd(&A[(size_t)ir*k + ic], 2.0f);
}

__global__ void k_join_inv(const int* __restrict__ e, int E, const int* __restrict__ cnt,
                           const int* __restrict__ bucket, const int* __restrict__ inv,
                           float* A, int k){
    int i = blockIdx.x*blockDim.x + threadIdx.x;
    if (i >= E) return;
    int s2 = e[i], d2 = e[E+i];
    if (s2 == d2) return;
    int ic = inv[s2];
    if (ic < 0) return;
    int c = min(cnt[d2], CAP);
    const int* b = bucket + d2*CAP;
    for (int t = 0; t < c; t++){
        int d1 = b[t];
        if (d1 == s2) continue;
        int ir = inv[d1];
        if (ir >= 0) atomicAdd(&A[(size_t)ir*k + ic], 1.0f);
    }
}

__global__ void k_spmm(const int* __restrict__ e, int E, const float* __restrict__ U,
                       float* Z, int F){
    int w = (blockIdx.x*blockDim.x + threadIdx.x) >> 5;
    int lane = threadIdx.x & 31;
    if (w >= E) return;
    int s = e[w], d = e[E+w];
    const float* ur = U + (size_t)s*F;
    float* zr = Z + (size_t)d*F;
    for (int f = lane; f < F; f += 32) atomicAdd(&zr[f], ur[f]);
}

// ---------------- dense helpers ----------------

// deg = rowsum(A) + fill; optional bf16 conversion of the row (fused f2b)
__global__ void k_deg(const float* __restrict__ A, int n, float* dinv, float* fill,
                      __nv_bfloat16* __restrict__ Ab){
    int row  = blockIdx.x*(blockDim.x >> 5) + (threadIdx.x >> 5);
    int lane = threadIdx.x & 31;
    if (row >= n) return;
    const float* r = A + (size_t)row*n;
    float s = 0.f;
    for (int j = lane; j < n; j += 32){
        float v = r[j];
        s += v;
        if (Ab) Ab[(size_t)row*n + j] = __float2bfloat16(v);
    }
    #pragma unroll
    for (int o = 16; o; o >>= 1) s += __shfl_xor_sync(0xffffffffu, s, o);
    if (lane == 0){
        float f = (r[row] == 0.0f) ? 2.0f : 0.0f;
        float deg = s + f;
        dinv[row] = (deg > 0.f) ? 1.0f/sqrtf(deg) : 0.0f;
        fill[row] = f;
    }
}

// Vectorized fp32 SIMT GEMM (no guards): M%BM==0, N%BN==0, kc%16==0
template<int BM,int BN,int TM,int TN>
__global__ void k_gemm_f4(
    const float* __restrict__ A, const float* __restrict__ B, float* __restrict__ part,
    int M, int N, int K, int kc)
{
    const int BK = 16;
    const int NT = (BM/TM)*(BN/TN);
    __shared__ float As[BK][BM+4];
    __shared__ float Bs[BK][BN];
    int tid = threadIdx.x;
    int tx = tid % (BN/TN), ty = tid / (BN/TN);
    int bm = blockIdx.y*BM, bn = blockIdx.x*BN;
    int k0 = blockIdx.z*kc;
    float acc[TM][TN] = {};
    for (int kb = k0; kb < k0 + kc; kb += BK){
        #pragma unroll
        for (int q = 0; q < (BM*4)/NT; q++){
            int idx = tid + q*NT;
            int row = idx >> 2, c4 = (idx & 3) << 2;
            float4 v = *reinterpret_cast<const float4*>(&A[(size_t)(bm+row)*K + kb + c4]);
            As[c4+0][row] = v.x; As[c4+1][row] = v.y;
            As[c4+2][row] = v.z; As[c4+3][row] = v.w;
        }
        #pragma unroll
        for (int q = 0; q < (4*BN)/NT; q++){
            int idx = tid + q*NT;
            int row = idx/(BN/4), c4 = (idx % (BN/4)) << 2;
            *reinterpret_cast<float4*>(&Bs[row][c4]) =
                *reinterpret_cast<const float4*>(&B[(size_t)(kb+row)*N + bn + c4]);
        }
        __syncthreads();
        #pragma unroll
        for (int k = 0; k < BK; k++){
            float a[TM], b[TN];
            #pragma unroll
            for (int i = 0; i < TM; i += 4)
                *reinterpret_cast<float4*>(&a[i]) = *reinterpret_cast<const float4*>(&As[k][ty*TM + i]);
            #pragma unroll
            for (int j = 0; j < TN; j += 4)
                *reinterpret_cast<float4*>(&b[j]) = *reinterpret_cast<const float4*>(&Bs[k][tx*TN + j]);
            #pragma unroll
            for (int i = 0; i < TM; i++)
                #pragma unroll
                for (int j = 0; j < TN; j++)
                    acc[i][j] += a[i]*b[j];
        }
        __syncthreads();
    }
    float* out = part + (size_t)blockIdx.z*M*N;
    #pragma unroll
    for (int i = 0; i < TM; i++){
        int gm = bm + ty*TM + i;
        #pragma unroll
        for (int j = 0; j < TN; j += 4){
            int gn = bn + tx*TN + j;
            *reinterpret_cast<float4*>(&out[(size_t)gm*N + gn]) =
                *reinterpret_cast<const float4*>(&acc[i][j]);
        }
    }
}

// bf16 WMMA GEMM (raw partials; M%64==0, N%64==0, kc%32==0)
__global__ void k_wmma(const __nv_bfloat16* __restrict__ A, const __nv_bfloat16* __restrict__ B,
                       float* __restrict__ out, int M, int N, int K, int kc)
{
    __shared__ __nv_bfloat16 As[64][40];
    __shared__ __nv_bfloat16 Bs[32][72];
    int tid = threadIdx.x;
    int warp = tid >> 5;
    int wr = warp >> 1, wc = warp & 1;
    int bm = blockIdx.y*64, bn = blockIdx.x*64;
    float* o = out + (size_t)blockIdx.z*M*N;

    wmma::fragment<wmma::accumulator, 16,16,16, float> fc[2][2];
    #pragma unroll
    for (int i = 0; i < 2; i++)
        #pragma unroll
        for (int j = 0; j < 2; j++)
            wmma::fill_fragment(fc[i][j], 0.0f);

    int k0 = blockIdx.z*kc;
    for (int kb = k0; kb < k0 + kc; kb += 32){
        #pragma unroll
        for (int q = 0; q < 2; q++){
            int idx = tid + q*128;
            int row = idx >> 2, c8 = (idx & 3) << 3;
            *reinterpret_cast<uint4*>(&As[row][c8]) =
                *reinterpret_cast<const uint4*>(&A[(size_t)(bm+row)*K + kb + c8]);
        }
        #pragma unroll
        for (int q = 0; q < 2; q++){
            int idx = tid + q*128;
            int row = idx >> 3, c8 = (idx & 7) << 3;
            *reinterpret_cast<uint4*>(&Bs[row][c8]) =
                *reinterpret_cast<const uint4*>(&B[(size_t)(kb+row)*N + bn + c8]);
        }
        __syncthreads();
        #pragma unroll
        for (int kf = 0; kf < 2; kf++){
            wmma::fragment<wmma::matrix_a, 16,16,16, __nv_bfloat16, wmma::row_major> fa[2];
            wmma::fragment<wmma::matrix_b, 16,16,16, __nv_bfloat16, wmma::row_major> fb[2];
            #pragma unroll
            for (int i = 0; i < 2; i++)
                wmma::load_matrix_sync(fa[i], &As[wr*32 + i*16][kf*16], 40);
            #pragma unroll
            for (int j = 0; j < 2; j++)
                wmma::load_matrix_sync(fb[j], &Bs[kf*16][wc*32 + j*16], 72);
            #pragma unroll
            for (int i = 0; i < 2; i++)
                #pragma unroll
                for (int j = 0; j < 2; j++)
                    wmma::mma_sync(fc[i][j], fa[i], fb[j], fc[i][j]);
        }
        __syncthreads();
    }
    #pragma unroll
    for (int i = 0; i < 2; i++)
        #pragma unroll
        for (int j = 0; j < 2; j++)
            wmma::store_matrix_sync(&o[(size_t)(bm + wr*32 + i*16)*N + bn + wc*32 + j*16],
                                    fc[i][j], N, wmma::mem_row_major);
}

// Fused skinny projection: U = dinv .* (X @ W). N<=128, K*NC2<=4096, M%16==0.
// X source: either x (row-major) or fused unpool(res,C | xprev via inv).
// Optional: 3-split bf16 Ucat output (N==64 only), optional zeroing of Z rows.
__global__ __launch_bounds__(256) void k_xw2(
    const float* __restrict__ x, const float* __restrict__ W, float* __restrict__ U,
    int M, int N, int K, const float* __restrict__ dinv,
    const float* __restrict__ res, int C, const float* __restrict__ xprev, int Fx,
    const int* __restrict__ invp,
    __nv_bfloat16* __restrict__ Ucat, float* __restrict__ Zzero, int ZF)
{
    __shared__ float2 Wsp[4096];
    __shared__ float  Xsf[128*16];
    int tid = threadIdx.x;
    int NC2 = (N > 64) ? 64 : 32;
    for (int idx = tid; idx < K*NC2; idx += 256){
        int k = idx / NC2, c2 = idx - k*NC2;
        int col = 2*c2;
        float wx = (col < N) ? W[k*N + col] : 0.f;
        float wy = (col+1 < N) ? W[k*N + col + 1] : 0.f;
        Wsp[idx] = make_float2(wx, wy);
    }
    int row0 = blockIdx.x*16;
    for (int idx = tid; idx < 16*K; idx += 256){
        int r = idx / K, k = idx - r*K;
        int grow = row0 + r;
        float v;
        if (res){
            if (k < C) v = res[(size_t)grow*C + k];
            else { int j = invp[grow]; v = (j >= 0) ? xprev[(size_t)j*Fx + (k - C)] : 0.f; }
        } else {
            v = x[(size_t)grow*K + k];
        }
        Xsf[k*16 + r] = v;
    }
    if (Zzero){
        for (int idx = tid; idx < 16*ZF; idx += 256)
            Zzero[(size_t)row0*ZF + idx] = 0.f;
    }
    __syncthreads();
    int warp = tid >> 5, lane = tid & 31;
    const float2* Xsp = reinterpret_cast<const float2*>(Xsf);
    float2 a0 = {0.f,0.f}, a1 = {0.f,0.f}, b0 = {0.f,0.f}, b1 = {0.f,0.f};
    if (N <= 64){
        #pragma unroll 4
        for (int k = 0; k < K; k++){
            float2 wv = Wsp[k*32 + lane];
            float2 xv = Xsp[k*8 + warp];
            a0.x += xv.x*wv.x; a0.y += xv.x*wv.y;
            a1.x += xv.y*wv.x; a1.y += xv.y*wv.y;
        }
    } else {
        #pragma unroll 4
        for (int k = 0; k < K; k++){
            float2 wv  = Wsp[k*64 + lane];
            float2 wv2 = Wsp[k*64 + 32 + lane];
            float2 xv  = Xsp[k*8 + warp];
            a0.x += xv.x*wv.x;  a0.y += xv.x*wv.y;
            a1.x += xv.y*wv.x;  a1.y += xv.y*wv.y;
            b0.x += xv.x*wv2.x; b0.y += xv.x*wv2.y;
            b1.x += xv.y*wv2.x; b1.y += xv.y*wv2.y;
        }
    }
    int gr0 = row0 + 2*warp, gr1 = gr0 + 1;
    float d0 = dinv[gr0], d1 = dinv[gr1];
    int col = 2*lane;
    auto stor = [&](int grow, int c, float v){
        U[(size_t)grow*N + c] = v;
        if (Ucat){
            __nv_bfloat16 aa = __float2bfloat16(v);
            float rr = v - __bfloat162float(aa);
            __nv_bfloat16 bb = __float2bfloat16(rr);
            float r2 = rr - __bfloat162float(bb);
            __nv_bfloat16* rowp = Ucat + (size_t)grow*192;
            rowp[c] = aa; rowp[64 + c] = bb; rowp[128 + c] = __float2bfloat16(r2);
        }
    };
    if (col < N)  { stor(gr0, col,   d0*a0.x); stor(gr1, col,   d1*a1.x); }
    if (col+1 < N){ stor(gr0, col+1, d0*a0.y); stor(gr1, col+1, d1*a1.y); }
    if (N > 64){
        int c2 = col + 64;
        if (c2 < N)  { U[(size_t)gr0*N + c2]   = d0*b0.x; U[(size_t)gr1*N + c2]   = d1*b1.x; }
        if (c2+1 < N){ U[(size_t)gr0*N + c2+1] = d0*b0.y; U[(size_t)gr1*N + c2+1] = d1*b1.y; }
    }
}

// Reduce SK partials (fixed order -> deterministic) + epilogue.
// flags: 4 zero diag, 8 scale dinv[m], 16 gcn epi, 32 relu
__global__ void k_redepi(float* out, const float* __restrict__ part, int SK, int M, int N,
                         int flags, const float* __restrict__ dinv, const float* __restrict__ fl,
                         const float* __restrict__ bias, const float* __restrict__ Uin)
{
    size_t idx = (size_t)blockIdx.x*blockDim.x + threadIdx.x;
    if (idx >= (size_t)M*N) return;
    int m = (int)(idx / N), n = (int)(idx % N);
    size_t MN = (size_t)M*N;
    float v = 0.f;
    for (int z = 0; z < SK; z++) v += part[z*MN + idx];
    if (flags & 16)      v = dinv[m]*(v + fl[m]*Uin[idx]) + bias[n];
    else if (flags & 8)  v *= dinv[m];
    if (flags & 32) v = fmaxf(v, 0.f);
    if ((flags & 4) && m == n) v = 0.f;
    out[idx] = v;
}

// Reduce for concatenated 3-split wmma: part[z][m][g*64+c], g=0..2; gcn epilogue.
__global__ void k_red3(float* out, const float* __restrict__ part, int SK, int M,
                       const float* __restrict__ dinv, const float* __restrict__ fl,
                       const float* __restrict__ bias, const float* __restrict__ Uin, int relu)
{
    int idx = blockIdx.x*blockDim.x + threadIdx.x;
    if (idx >= M*64) return;
    int m = idx >> 6, c = idx & 63;
    size_t MN = (size_t)M*192;
    float v = 0.f;
    for (int z = 0; z < SK; z++){
        const float* p = part + z*MN + (size_t)m*192;
        v += p[c] + p[64 + c] + p[128 + c];
    }
    v = dinv[m]*(v + fl[m]*Uin[idx]) + bias[c];
    if (relu) v = fmaxf(v, 0.f);
    out[idx] = v;
}

// ---------------- augment operand gathers (diag folded in) ----------------

__global__ void k_gather_rows(const float* __restrict__ A, int n, const int* __restrict__ perm,
                              float* Gr, int k){
    size_t t = (size_t)blockIdx.x*blockDim.x + threadIdx.x;
    size_t tot = (size_t)k*(n/4);
    if (t >= tot) return;
    int r = (int)(t / (n/4));
    int c4 = (int)(t % (n/4))*4;
    int pr = perm[r];
    float4 v = *reinterpret_cast<const float4*>(&A[(size_t)pr*n + c4]);
    if (pr >= c4 && pr < c4 + 4) (&v.x)[pr - c4] += 1.0f;
    *reinterpret_cast<float4*>(&Gr[(size_t)r*n + c4]) = v;
}
__global__ void k_gather_cols(const float* __restrict__ A, int n, const int* __restrict__ perm,
                              float* Gc, int k){
    size_t t = (size_t)blockIdx.x*blockDim.x + threadIdx.x;
    if (t >= (size_t)n*k) return;
    int j = (int)(t / k), c = (int)(t % k);
    int pc = perm[c];
    Gc[t] = A[(size_t)j*n + pc] + ((j == pc) ? 1.f : 0.f);
}
__global__ void k_gather_rows_bf(const float* __restrict__ A, int n, const int* __restrict__ perm,
                                 __nv_bfloat16* Gr, int k){
    size_t t = (size_t)blockIdx.x*blockDim.x + threadIdx.x;
    if (t >= (size_t)k*n) return;
    int r = (int)(t / n), c = (int)(t % n);
    int pr = perm[r];
    float v = A[(size_t)pr*n + c] + ((c == pr) ? 1.f : 0.f);
    Gr[t] = __float2bfloat16(v);
}
__global__ void k_gather_cols_bf(const float* __restrict__ A, int n, const int* __restrict__ perm,
                                 __nv_bfloat16* Gc, int k){
    size_t t = (size_t)blockIdx.x*blockDim.x + threadIdx.x;
    if (t >= (size_t)n*k) return;
    int j = (int)(t / k), c = (int)(t % k);
    int pc = perm[c];
    float v = A[(size_t)j*n + pc] + ((j == pc) ? 1.f : 0.f);
    Gc[t] = __float2bfloat16(v);
}

// ---------------- gcn epilogue (sparse path) ----------------

__global__ void k_gcn_epi(const float* Z, const float* U, const float* dinv, const float* fill,
                          const float* __restrict__ b, float* out, int n, int F, int relu){
    int idx = blockIdx.x*blockDim.x + threadIdx.x;
    if (idx >= n*F) return;
    int i = idx / F, f = idx % F;
    float v = dinv[i]*(Z[idx] + fill[i]*U[idx]) + b[f];
    if (relu) v = fmaxf(v, 0.f);
    out[idx] = v;
}

// ---------------- topk / unpool / misc ----------------

// fused ||w|| + inline scoring + partial rank counting (no atomics, no pre-zero)
__global__ void k_topk_cnt(const float* __restrict__ x, int n, int F,
                           const float* __restrict__ w, int* tcnt, float* score){
    __shared__ float ws[256];
    __shared__ float shr[256];
    __shared__ float sj[256];
    int tid = threadIdx.x;
    float wv = (tid < F) ? w[tid] : 0.f;
    ws[tid] = wv;
    shr[tid] = wv*wv;
    __syncthreads();
    for (int o = 128; o; o >>= 1){
        if (tid < o) shr[tid] += shr[tid + o];
        __syncthreads();
    }
    float inv_nrm = 1.0f / sqrtf(shr[0]);
    int i = blockIdx.x*256 + tid;
    const float* xr = x + (size_t)i*F;
    float si = 0.f;
    for (int f = 0; f < F; f++) si += xr[f]*ws[f];
    si = tanhf(si * inv_nrm);
    if (blockIdx.y == 0) score[i] = si;
    int chunk = n / gridDim.y;
    int j0 = blockIdx.y * chunk;
    int c = 0;
    for (int jb = j0; jb < j0 + chunk; jb += 256){
        {
            int j = jb + tid;
            const float* xj = x + (size_t)j*F;
            float s = 0.f;
            for (int f = 0; f < F; f++) s += xj[f]*ws[f];
            __syncthreads();
            sj[tid] = tanhf(s * inv_nrm);
        }
        __syncthreads();
        #pragma unroll 8
        for (int t = 0; t < 256; t++){
            float v = sj[t]; int j = jb + t;
            c += (v > si) || (v == si && j < i);
        }
    }
    tcnt[blockIdx.y*n + i] = c;
}

// fused: sum partial ranks + place perm + inverse perm + gathered/scaled features
__global__ void k_topk_fin(const float* __restrict__ s, const int* __restrict__ tcnt, int chy,
                           const float* __restrict__ x, int F, int n, int k,
                           int* perm, int* inv, float* xg){
    int node = (blockIdx.x*blockDim.x + threadIdx.x) >> 5;
    int lane = threadIdx.x & 31;
    if (node >= n) return;
    int c = 0;
    for (int y = 0; y < chy; y++) c += tcnt[y*n + node];
    bool keep = c < k;
    if (lane == 0){
        if (keep) perm[c] = node;
        inv[node] = keep ? c : -1;
    }
    if (!keep) return;
    float sv = s[node];
    const float* xr = x + (size_t)node*F;
    float* o = xg + (size_t)c*F;
    for (int f = lane; f < F; f += 32) o[f] = xr[f]*sv;
}

// unpool (kept for up0/up1 whose GCN uses the g64 path)
__global__ void k_unpool(const float* __restrict__ res, int C,
                         const float* __restrict__ xprev, int Fx,
                         const int* __restrict__ inv, float* out, int n){
    int t = blockIdx.x*blockDim.x + threadIdx.x;
    int W = 2*C;
    if (t >= n*W) return;
    int r = t / W, f = t % W;
    float v;
    if (f < C) v = res[(size_t)r*C + f];
    else {
        int j = inv[r];
        v = (j >= 0) ? xprev[(size_t)j*Fx + (f - C)] : 0.f;
    }
    out[t] = v;
}

__global__ void k_softmax(const float* z, float* out, int n, int C){
    int i = blockIdx.x*blockDim.x + threadIdx.x;
    if (i >= n) return;
    const float* r = z + (size_t)i*C;
    float m = -1e30f;
    for (int c = 0; c < C; c++) m = fmaxf(m, r[c]);
    float s = 0.f;
    for (int c = 0; c < C; c++) s += expf(r[c] - m);
    float inv = 1.0f/s;
    for (int c = 0; c < C; c++) out[(size_t)i*C + c] = expf(r[c] - m)*inv;
}

// ---------------- host orchestration ----------------

extern "C" void kernel_launch(void* const* d_in, const int* in_sizes, int n_in,
                              void* d_out, int out_size){
    const float* x_in = (const float*)d_in[0];
    const int*   eidx = (const int*)d_in[1];
    const float *Wd[5], *bd[5], *pv[4], *Wu[4], *bu[4];
    for (int i = 0; i < 5; i++){ Wd[i] = (const float*)d_in[2 + 2*i]; bd[i] = (const float*)d_in[3 + 2*i]; }
    for (int i = 0; i < 4; i++)  pv[i] = (const float*)d_in[12 + i];
    for (int i = 0; i < 4; i++){ Wu[i] = (const float*)d_in[16 + 2*i]; bu[i] = (const float*)d_in[17 + 2*i]; }
    const float* Wo = (const float*)d_in[24];
    const float* bo = (const float*)d_in[25];
    int E = in_sizes[1] / 2;

    float *pS,*pAs1,*pAs2,*pAs3,*pA4;
    float *px0,*px1,*px2,*px3,*px4,*pxg,*pxu,*pxcat,*pU,*pZ;
    float *pscore;
    float *pdinv[5], *pfill[5];
    __nv_bfloat16 *pUcat;
    int *pperm[4],*pinvl[4],*piz,*ptcnt,*pbucket;
    cudaGetSymbolAddress((void**)&pS,    g_S);
    cudaGetSymbolAddress((void**)&pAs1,  g_As1);
    cudaGetSymbolAddress((void**)&pAs2,  g_As2);
    cudaGetSymbolAddress((void**)&pAs3,  g_As3);
    cudaGetSymbolAddress((void**)&pA4,   g_A4);
    cudaGetSymbolAddress((void**)&px0,   g_x0);
    cudaGetSymbolAddress((void**)&px1,   g_x1);
    cudaGetSymbolAddress((void**)&px2,   g_x2);
    cudaGetSymbolAddress((void**)&px3,   g_x3);
    cudaGetSymbolAddress((void**)&px4,   g_x4);
    cudaGetSymbolAddress((void**)&pxg,   g_xg);
    cudaGetSymbolAddress((void**)&pxu,   g_xu);
    cudaGetSymbolAddress((void**)&pxcat, g_xcat);
    cudaGetSymbolAddress((void**)&pU,    g_bU);
    cudaGetSymbolAddress((void**)&pZ,    g_bZ);
    cudaGetSymbolAddress((void**)&pUcat, g_Ucat);
    cudaGetSymbolAddress((void**)&pdinv[0], g_dinv0); cudaGetSymbolAddress((void**)&pfill[0], g_fill0);
    cudaGetSymbolAddress((void**)&pdinv[1], g_dinv1); cudaGetSymbolAddress((void**)&pfill[1], g_fill1);
    cudaGetSymbolAddress((void**)&pdinv[2], g_dinv2); cudaGetSymbolAddress((void**)&pfill[2], g_fill2);
    cudaGetSymbolAddress((void**)&pdinv[3], g_dinv3); cudaGetSymbolAddress((void**)&pfill[3], g_fill3);
    cudaGetSymbolAddress((void**)&pdinv[4], g_dinv4); cudaGetSymbolAddress((void**)&pfill[4], g_fill4);
    cudaGetSymbolAddress((void**)&pscore, g_score);
    cudaGetSymbolAddress((void**)&pperm[0], g_perm0);
    cudaGetSymbolAddress((void**)&pperm[1], g_perm1);
    cudaGetSymbolAddress((void**)&pperm[2], g_perm2);
    cudaGetSymbolAddress((void**)&pperm[3], g_perm3);
    cudaGetSymbolAddress((void**)&pinvl[0], g_inv0);
    cudaGetSymbolAddress((void**)&pinvl[1], g_inv1);
    cudaGetSymbolAddress((void**)&pinvl[2], g_inv2);
    cudaGetSymbolAddress((void**)&pinvl[3], g_inv3);
    cudaGetSymbolAddress((void**)&piz,    g_iz);
    cudaGetSymbolAddress((void**)&ptcnt,  g_tcnt);
    cudaGetSymbolAddress((void**)&pbucket,g_bucket);
    int* pdegi  = piz;
    int* pselfc = piz + 4096;
    int* pcnt   = piz + 8192;

    char* base = (char*)pS;
    float* pGr   = pS;
    float* pGc   = pS + 4194304;
    float* ppart = pS + 8388608;
    __nv_bfloat16* pA1b = (__nv_bfloat16*)(base + (size_t)48*1024*1024);
    __nv_bfloat16* pGrb = (__nv_bfloat16*)(base + (size_t)56*1024*1024);
    __nv_bfloat16* pGcb = (__nv_bfloat16*)(base + (size_t)60*1024*1024);

    auto g64 = [&](const float* A, const float* B, int M, int N, int K, int SK){
        dim3 g(N/64, M/64, SK);
        k_gemm_f4<64,64,8,8><<<g,64>>>(A,B,ppart,M,N,K,K/SK);
    };
    auto red = [&](float* out, int SK, int M, int N, int flags,
                   const float* dv, const float* fl, const float* bias, const float* Uin){
        size_t tot = (size_t)M*N;
        k_redepi<<<(unsigned)((tot + 255)/256), 256>>>(out, ppart, SK, M, N, flags, dv, fl, bias, Uin);
    };
    auto xw = [&](const float* x, const float* W, int n, int fout, int fin, const float* dv,
                  const float* res, int C, const float* xprev, int Fx, const int* inv,
                  __nv_bfloat16* Ucat, float* Zz, int ZF){
        k_xw2<<<n/16, 256>>>(x, W, pU, n, fout, fin, dv, res, C, xprev, Fx, inv, Ucat, Zz, ZF);
    };
    auto topk = [&](const float* x, int n, int F, const float* w, int k, int lvl, float* xg){
        int chy = n/256 < 8 ? n/256 : 8;
        dim3 gr(n/256, chy);
        k_topk_cnt<<<gr, 256>>>(x, n, F, w, ptcnt, pscore);
        k_topk_fin<<<(n*32 + 255)/256, 256>>>(pscore, ptcnt, chy, x, F, n, k, pperm[lvl], pinvl[lvl], xg);
    };
    auto gcnD = [&](const float* A, int n, const float* dv, const float* fl,
                    const float* x, int fin, const float* W, const float* b,
                    int fout, float* out, bool relu){
        bool usexw = (fout <= 64 && fin <= 128) || (fout <= 128 && fin <= 64);
        if (usexw){
            xw(x, W, n, fout, fin, dv, nullptr,0,nullptr,0,nullptr, nullptr, nullptr, 0);
        } else {
            g64(x, W, n, fout, fin, 4);
            red(pU, 4, n, fout, 8, dv, nullptr, nullptr, nullptr);
        }
        g64(A, pU, n, fout, n, 16);
        red(out, 16, n, fout, 16 | (relu ? 32 : 0), dv, fl, b, pU);
    };
    // level-1 GCN via bf16 TC: As1 exact bf16, U 3-split concatenated in xw epilogue
    auto gcnTC1 = [&](const float* x, int fin, const float* W, const float* b,
                      float* out, bool relu,
                      const float* res, int C, const float* xprev, int Fx, const int* inv){
        xw(x, W, 2048, 64, fin, pdinv[1], res, C, xprev, Fx, inv, pUcat, nullptr, 0);
        const int SK = 8;
        dim3 g(3, 2048/64, SK);
        k_wmma<<<g,128>>>(pA1b, pUcat, ppart, 2048, 192, 2048, 2048/SK);
        k_red3<<<(2048*64 + 255)/256, 256>>>(out, ppart, SK, 2048, pdinv[1], pfill[1], b, pU, relu ? 1 : 0);
    };
    auto gcn0 = [&](const float* x, int fin, const float* W, const float* b,
                    int fout, float* out, bool relu,
                    const float* res, int C, const float* xprev, int Fx, const int* inv){
        xw(x, W, 4096, fout, fin, pdinv[0], res, C, xprev, Fx, inv, nullptr, pZ, fout);
        k_spmm<<<(E*32 + 255)/256, 256>>>(eidx, E, pU, pZ, fout);
        int tot = 4096*fout;
        k_gcn_epi<<<(tot + 255)/256, 256>>>(pZ, pU, pdinv[0], pfill[0], b, out, 4096, fout, relu ? 1 : 0);
    };
    auto aug = [&](const float* Asrc, int n, const int* perm, int k, float* Adst){
        size_t rt = (size_t)k*(n/4);
        k_gather_rows<<<(unsigned)((rt + 255)/256), 256>>>(Asrc, n, perm, pGr, k);
        size_t ct = (size_t)n*k;
        k_gather_cols<<<(unsigned)((ct + 255)/256), 256>>>(Asrc, n, perm, pGc, k);
        int SK = (k >= 512) ? 4 : 8;
        g64(pGr, pGc, k, k, n, SK);
        red(Adst, SK, k, k, 4, nullptr, nullptr, nullptr, nullptr);
    };

    // ---- level-0 degrees + buckets ----
    cudaMemsetAsync(piz, 0, 3*4096*sizeof(int), 0);
    k_edge_stats<<<(E + 255)/256, 256>>>(eidx, E, pdegi, pselfc);
    k_deg0_fin<<<(4096 + 255)/256, 256>>>(pdegi, pselfc, pdinv[0], pfill[0], 4096);
    k_bucket_fill<<<(E + 255)/256, 256>>>(eidx, E, pcnt, pbucket);

    // ---- down level 0 (sparse) ----
    gcn0(x_in, 128, Wd[0], bd[0], 32, px0, true, nullptr,0,nullptr,0,nullptr);

    // ---- pool to 2048; build As1 via sparse join; deg + bf16 fused ----
    topk(px0, 4096, 32, pv[0], 2048, 0, pxg);
    cudaMemsetAsync(pAs1, 0, (size_t)2048*2048*sizeof(float), 0);
    k_scatter_aug_inv<<<(E + 255)/256, 256>>>(eidx, E, pinvl[0], pAs1, 2048);
    k_join_inv<<<(E + 255)/256, 256>>>(eidx, E, pcnt, pbucket, pinvl[0], pAs1, 2048);
    k_deg<<<(2048 + 7)/8, 256>>>(pAs1, 2048, pdinv[1], pfill[1], pA1b);
    gcnTC1(pxg, 32, Wd[1], bd[1], px1, true, nullptr,0,nullptr,0,nullptr);

    // ---- level 2: pooled augment via bf16 wmma ----
    topk(px1, 2048, 64, pv[1], 1024, 1, pxg);
    {
        size_t rt = (size_t)1024*2048;
        k_gather_rows_bf<<<(unsigned)((rt + 255)/256), 256>>>(pAs1, 2048, pperm[1], pGrb, 1024);
        k_gather_cols_bf<<<(unsigned)((rt + 255)/256), 256>>>(pAs1, 2048, pperm[1], pGcb, 1024);
        dim3 g(1024/64, 1024/64, 2);
        k_wmma<<<g,128>>>(pGrb, pGcb, ppart, 1024, 1024, 2048, 1024);
        red(pAs2, 2, 1024, 1024, 4, nullptr, nullptr, nullptr, nullptr);
    }
    k_deg<<<(1024 + 7)/8, 256>>>(pAs2, 1024, pdinv[2], pfill[2], nullptr);
    gcnD(pAs2, 1024, pdinv[2], pfill[2], pxg, 64, Wd[2], bd[2], 128, px2, true);

    // ---- level 3 ----
    topk(px2, 1024, 128, pv[2], 512, 2, pxg);
    aug(pAs2, 1024, pperm[2], 512, pAs3);
    k_deg<<<(512 + 7)/8, 256>>>(pAs3, 512, pdinv[3], pfill[3], nullptr);
    gcnD(pAs3, 512, pdinv[3], pfill[3], pxg, 128, Wd[3], bd[3], 256, px3, true);

    // ---- level 4 ----
    topk(px3, 512, 256, pv[3], 256, 3, pxg);
    aug(pAs3, 512, pperm[3], 256, pA4);
    k_deg<<<(256 + 7)/8, 256>>>(pA4, 256, pdinv[4], pfill[4], nullptr);
    gcnD(pA4, 256, pdinv[4], pfill[4], pxg, 256, Wd[4], bd[4], 512, px4, true);

    // ---- up path ----
    k_unpool<<<(512*512 + 255)/256, 256>>>(px3, 256, px4, 512, pinvl[3], pxcat, 512);
    gcnD(pAs3, 512, pdinv[3], pfill[3], pxcat, 512, Wu[0], bu[0], 256, pxu, true);

    k_unpool<<<(1024*256 + 255)/256, 256>>>(px2, 128, pxu, 256, pinvl[2], pxcat, 1024);
    gcnD(pAs2, 1024, pdinv[2], pfill[2], pxcat, 256, Wu[1], bu[1], 128, pxu, true);

    // up2: unpool fused into xw (res=x1 C=64, prev=xu Fx=128)
    gcnTC1(nullptr, 128, Wu[2], bu[2], pxu, true, px1, 64, pxu, 128, pinvl[1]);

    // up3: unpool fused into xw (res=x0 C=32, prev=xu Fx=64), NO relu
    gcn0(nullptr, 64, Wu[3], bu[3], 32, pxu, false, px0, 32, pxu, 64, pinvl[0]);

    // ---- final GCN (sparse) + softmax ----
    gcn0(pxu, 32, Wo, bo, 37, pxcat, false, nullptr,0,nullptr,0,nullptr);
    k_softmax<<<(4096 + 255)/256, 256>>>(pxcat, (float*)d_out, 4096, 37);
}

// round 17
// speedup vs baseline: 1.6733x; 1.6733x over previous
#include <cuda_runtime.h>
#include <cuda_bf16.h>
#include <mma.h>
#include <math.h>

using namespace nvcuda;

#define CAP 192

// ---------------- static device scratch (no allocation allowed) ----------------
__device__ float g_S[(size_t)4096*4096];      // [0,16M) Gr | [16,32M) Gc | [32,48M) part | [48,56M) A1b | [56,60M) Grb | [60,64M) Gcb
__device__ float g_As1[(size_t)2048*2048];
__device__ float g_As2[(size_t)1024*1024];
__device__ float g_As3[(size_t)512*512];
__device__ float g_A4[(size_t)256*256];
__device__ float g_x0[4096*32];
__device__ float g_x1[2048*64];
__device__ float g_x2[1024*128];
__device__ float g_x3[512*256];
__device__ float g_x4[256*512];
__device__ float g_xg[2048*64];
__device__ float g_xu[4096*64];
__device__ float g_xcat[4096*64];
__device__ float g_bU[4096*64];
__device__ float g_bZ[4096*64];
__device__ __nv_bfloat16 g_Ucat[2048*192];
__device__ float g_dinv0[4096], g_fill0[4096];
__device__ float g_dinv1[2048], g_fill1[2048];
__device__ float g_dinv2[1024], g_fill2[1024];
__device__ float g_dinv3[512],  g_fill3[512];
__device__ float g_dinv4[256],  g_fill4[256];
__device__ float g_score[4096];
__device__ int   g_perm0[2048];
__device__ int   g_perm1[1024];
__device__ int   g_perm2[512];
__device__ int   g_perm3[256];
__device__ int   g_iz[4096*3];                // degi | selfc | cnt (one memset)
__device__ int   g_tcnt[4096*8];              // per-chunk partial ranks (no memset needed)
__device__ int   g_inv0[4096];
__device__ int   g_inv1[2048];
__device__ int   g_inv2[1024];
__device__ int   g_inv3[512];
__device__ int   g_bucket[4096*CAP];

// ---------------- sparse level-0 kernels ----------------

__global__ void k_edge_stats(const int* __restrict__ e, int E, int* degi, int* selfc){
    int i = blockIdx.x*blockDim.x + threadIdx.x;
    if (i >= E) return;
    int s = e[i], d = e[E+i];
    atomicAdd(&degi[d], 1);
    if (s == d) atomicAdd(&selfc[d], 1);
}

__global__ void k_deg0_fin(const int* __restrict__ degi, const int* __restrict__ selfc,
                           float* dinv, float* fill, int n){
    int i = blockIdx.x*blockDim.x + threadIdx.x;
    if (i >= n) return;
    float f = (selfc[i] == 0) ? 2.0f : 0.0f;
    float deg = (float)degi[i] + f;
    dinv[i] = (deg > 0.f) ? 1.0f/sqrtf(deg) : 0.0f;
    fill[i] = f;
}

__global__ void k_bucket_fill(const int* __restrict__ e, int E, int* cnt, int* bucket){
    int i = blockIdx.x*blockDim.x + threadIdx.x;
    if (i >= E) return;
    int s = e[i], d = e[E+i];
    if (s == d) return;
    int p = atomicAdd(&cnt[s], 1);
    if (p < CAP) bucket[s*CAP + p] = d;
}

__global__ void k_scatter_aug_inv(const int* __restrict__ e, int E, const int* __restrict__ inv,
                                  float* A, int k){
    int i = blockIdx.x*blockDim.x + threadIdx.x;
    if (i >= E) return;
    int s = e[i], d = e[E+i];
    if (s == d) return;
    int ir = inv[d], ic = inv[s];
    if (ir >= 0 && ic >= 0) atomicAdd(&A[(size_t)ir*k + ic], 2.0f);
}

__global__ void k_join_inv(const int* __restrict__ e, int E, const int* __restrict__ cnt,
                           const int* __restrict__ bucket, const int* __restrict__ inv,
                           float* A, int k){
    int i = blockIdx.x*blockDim.x + threadIdx.x;
    if (i >= E) return;
    int s2 = e[i], d2 = e[E+i];
    if (s2 == d2) return;
    int ic = inv[s2];
    if (ic < 0) return;
    int c = min(cnt[d2], CAP);
    const int* b = bucket + d2*CAP;
    for (int t = 0; t < c; t++){
        int d1 = b[t];
        if (d1 == s2) continue;
        int ir = inv[d1];
        if (ir >= 0) atomicAdd(&A[(size_t)ir*k + ic], 1.0f);
    }
}

__global__ void k_spmm(const int* __restrict__ e, int E, const float* __restrict__ U,
                       float* Z, int F){
    int w = (blockIdx.x*blockDim.x + threadIdx.x) >> 5;
    int lane = threadIdx.x & 31;
    if (w >= E) return;
    int s = e[w], d = e[E+w];
    const float* ur = U + (size_t)s*F;
    float* zr = Z + (size_t)d*F;
    for (int f = lane; f < F; f += 32) atomicAdd(&zr[f], ur[f]);
}

// ---------------- dense helpers ----------------

// deg = rowsum(A) + fill; optional fused bf16 conversion of the row
__global__ void k_deg(const float* __restrict__ A, int n, float* dinv, float* fill,
                      __nv_bfloat16* __restrict__ Ab){
    int row  = blockIdx.x*(blockDim.x >> 5) + (threadIdx.x >> 5);
    int lane = threadIdx.x & 31;
    if (row >= n) return;
    const float* r = A + (size_t)row*n;
    float s = 0.f;
    for (int j = lane; j < n; j += 32){
        float v = r[j];
        s += v;
        if (Ab) Ab[(size_t)row*n + j] = __float2bfloat16(v);
    }
    #pragma unroll
    for (int o = 16; o; o >>= 1) s += __shfl_xor_sync(0xffffffffu, s, o);
    if (lane == 0){
        float f = (r[row] == 0.0f) ? 2.0f : 0.0f;
        float deg = s + f;
        dinv[row] = (deg > 0.f) ? 1.0f/sqrtf(deg) : 0.0f;
        fill[row] = f;
    }
}

// Vectorized fp32 SIMT GEMM (no guards): M%BM==0, N%BN==0, kc%16==0
template<int BM,int BN,int TM,int TN>
__global__ void k_gemm_f4(
    const float* __restrict__ A, const float* __restrict__ B, float* __restrict__ part,
    int M, int N, int K, int kc)
{
    const int BK = 16;
    const int NT = (BM/TM)*(BN/TN);
    __shared__ float As[BK][BM+4];
    __shared__ float Bs[BK][BN];
    int tid = threadIdx.x;
    int tx = tid % (BN/TN), ty = tid / (BN/TN);
    int bm = blockIdx.y*BM, bn = blockIdx.x*BN;
    int k0 = blockIdx.z*kc;
    float acc[TM][TN] = {};
    for (int kb = k0; kb < k0 + kc; kb += BK){
        #pragma unroll
        for (int q = 0; q < (BM*4)/NT; q++){
            int idx = tid + q*NT;
            int row = idx >> 2, c4 = (idx & 3) << 2;
            float4 v = *reinterpret_cast<const float4*>(&A[(size_t)(bm+row)*K + kb + c4]);
            As[c4+0][row] = v.x; As[c4+1][row] = v.y;
            As[c4+2][row] = v.z; As[c4+3][row] = v.w;
        }
        #pragma unroll
        for (int q = 0; q < (4*BN)/NT; q++){
            int idx = tid + q*NT;
            int row = idx/(BN/4), c4 = (idx % (BN/4)) << 2;
            *reinterpret_cast<float4*>(&Bs[row][c4]) =
                *reinterpret_cast<const float4*>(&B[(size_t)(kb+row)*N + bn + c4]);
        }
        __syncthreads();
        #pragma unroll
        for (int k = 0; k < BK; k++){
            float a[TM], b[TN];
            #pragma unroll
            for (int i = 0; i < TM; i += 4)
                *reinterpret_cast<float4*>(&a[i]) = *reinterpret_cast<const float4*>(&As[k][ty*TM + i]);
            #pragma unroll
            for (int j = 0; j < TN; j += 4)
                *reinterpret_cast<float4*>(&b[j]) = *reinterpret_cast<const float4*>(&Bs[k][tx*TN + j]);
            #pragma unroll
            for (int i = 0; i < TM; i++)
                #pragma unroll
                for (int j = 0; j < TN; j++)
                    acc[i][j] += a[i]*b[j];
        }
        __syncthreads();
    }
    float* out = part + (size_t)blockIdx.z*M*N;
    #pragma unroll
    for (int i = 0; i < TM; i++){
        int gm = bm + ty*TM + i;
        #pragma unroll
        for (int j = 0; j < TN; j += 4){
            int gn = bn + tx*TN + j;
            *reinterpret_cast<float4*>(&out[(size_t)gm*N + gn]) =
                *reinterpret_cast<const float4*>(&acc[i][j]);
        }
    }
}

// bf16 WMMA GEMM (raw partials; M%64==0, N%64==0, kc%32==0)
__global__ void k_wmma(const __nv_bfloat16* __restrict__ A, const __nv_bfloat16* __restrict__ B,
                       float* __restrict__ out, int M, int N, int K, int kc)
{
    __shared__ __nv_bfloat16 As[64][40];
    __shared__ __nv_bfloat16 Bs[32][72];
    int tid = threadIdx.x;
    int warp = tid >> 5;
    int wr = warp >> 1, wc = warp & 1;
    int bm = blockIdx.y*64, bn = blockIdx.x*64;
    float* o = out + (size_t)blockIdx.z*M*N;

    wmma::fragment<wmma::accumulator, 16,16,16, float> fc[2][2];
    #pragma unroll
    for (int i = 0; i < 2; i++)
        #pragma unroll
        for (int j = 0; j < 2; j++)
            wmma::fill_fragment(fc[i][j], 0.0f);

    int k0 = blockIdx.z*kc;
    for (int kb = k0; kb < k0 + kc; kb += 32){
        #pragma unroll
        for (int q = 0; q < 2; q++){
            int idx = tid + q*128;
            int row = idx >> 2, c8 = (idx & 3) << 3;
            *reinterpret_cast<uint4*>(&As[row][c8]) =
                *reinterpret_cast<const uint4*>(&A[(size_t)(bm+row)*K + kb + c8]);
        }
        #pragma unroll
        for (int q = 0; q < 2; q++){
            int idx = tid + q*128;
            int row = idx >> 3, c8 = (idx & 7) << 3;
            *reinterpret_cast<uint4*>(&Bs[row][c8]) =
                *reinterpret_cast<const uint4*>(&B[(size_t)(kb+row)*N + bn + c8]);
        }
        __syncthreads();
        #pragma unroll
        for (int kf = 0; kf < 2; kf++){
            wmma::fragment<wmma::matrix_a, 16,16,16, __nv_bfloat16, wmma::row_major> fa[2];
            wmma::fragment<wmma::matrix_b, 16,16,16, __nv_bfloat16, wmma::row_major> fb[2];
            #pragma unroll
            for (int i = 0; i < 2; i++)
                wmma::load_matrix_sync(fa[i], &As[wr*32 + i*16][kf*16], 40);
            #pragma unroll
            for (int j = 0; j < 2; j++)
                wmma::load_matrix_sync(fb[j], &Bs[kf*16][wc*32 + j*16], 72);
            #pragma unroll
            for (int i = 0; i < 2; i++)
                #pragma unroll
                for (int j = 0; j < 2; j++)
                    wmma::mma_sync(fc[i][j], fa[i], fb[j], fc[i][j]);
        }
        __syncthreads();
    }
    #pragma unroll
    for (int i = 0; i < 2; i++)
        #pragma unroll
        for (int j = 0; j < 2; j++)
            wmma::store_matrix_sync(&o[(size_t)(bm + wr*32 + i*16)*N + bn + wc*32 + j*16],
                                    fc[i][j], N, wmma::mem_row_major);
}

// Fused skinny projection: U = dinv .* (x @ W). N<=64, K<=128, M%16==0. (R13 version)
__global__ __launch_bounds__(256) void k_xw2(const float* __restrict__ x,
                                             const float* __restrict__ W,
                                             float* __restrict__ U,
                                             int M, int N, int K,
                                             const float* __restrict__ dinv){
    __shared__ float Ws[128][64];
    __shared__ float Xs[16][128];
    int tid = threadIdx.x;
    for (int idx = tid; idx < K*64; idx += 256){
        int k = idx >> 6, c = idx & 63;
        Ws[k][c] = (c < N) ? W[k*N + c] : 0.f;
    }
    int row0 = blockIdx.x*16;
    for (int idx = tid; idx < 16*K; idx += 256){
        int r = idx / K, k = idx - r*K;
        Xs[r][k] = x[(size_t)(row0 + r)*K + k];
    }
    __syncthreads();
    int warp = tid >> 5, lane = tid & 31;
    int r0 = warp*2, r1 = r0 + 1;
    float a00 = 0.f, a01 = 0.f, a10 = 0.f, a11 = 0.f;
    for (int k = 0; k < K; k++){
        float wa = Ws[k][lane], wb = Ws[k][lane + 32];
        float x0 = Xs[r0][k], x1 = Xs[r1][k];
        a00 += x0*wa; a01 += x0*wb;
        a10 += x1*wa; a11 += x1*wb;
    }
    int gr0 = row0 + r0, gr1 = row0 + r1;
    float d0 = dinv[gr0], d1 = dinv[gr1];
    if (lane < N){
        U[(size_t)gr0*N + lane] = d0 * a00;
        U[(size_t)gr1*N + lane] = d1 * a10;
    }
    if (lane + 32 < N){
        U[(size_t)gr0*N + lane + 32] = d0 * a01;
        U[(size_t)gr1*N + lane + 32] = d1 * a11;
    }
}

// Reduce SK partials (fixed order -> deterministic) + epilogue.
// flags: 4 zero diag, 8 scale dinv[m], 16 gcn epi, 32 relu
__global__ void k_redepi(float* out, const float* __restrict__ part, int SK, int M, int N,
                         int flags, const float* __restrict__ dinv, const float* __restrict__ fl,
                         const float* __restrict__ bias, const float* __restrict__ Uin)
{
    size_t idx = (size_t)blockIdx.x*blockDim.x + threadIdx.x;
    if (idx >= (size_t)M*N) return;
    int m = (int)(idx / N), n = (int)(idx % N);
    size_t MN = (size_t)M*N;
    float v = 0.f;
    for (int z = 0; z < SK; z++) v += part[z*MN + idx];
    if (flags & 16)      v = dinv[m]*(v + fl[m]*Uin[idx]) + bias[n];
    else if (flags & 8)  v *= dinv[m];
    if (flags & 32) v = fmaxf(v, 0.f);
    if ((flags & 4) && m == n) v = 0.f;
    out[idx] = v;
}

// Reduce for concatenated 3-split wmma: part[z][m][g*64+c], g=0..2; gcn epilogue.
__global__ void k_red3(float* out, const float* __restrict__ part, int SK, int M,
                       const float* __restrict__ dinv, const float* __restrict__ fl,
                       const float* __restrict__ bias, const float* __restrict__ Uin, int relu)
{
    int idx = blockIdx.x*blockDim.x + threadIdx.x;
    if (idx >= M*64) return;
    int m = idx >> 6, c = idx & 63;
    size_t MN = (size_t)M*192;
    float v = 0.f;
    for (int z = 0; z < SK; z++){
        const float* p = part + z*MN + (size_t)m*192;
        v += p[c] + p[64 + c] + p[128 + c];
    }
    v = dinv[m]*(v + fl[m]*Uin[idx]) + bias[c];
    if (relu) v = fmaxf(v, 0.f);
    out[idx] = v;
}

// ---------------- conversion kernels ----------------

// 3-term bf16 split into concatenated layout: Ucat[r][0:64)=h, [64:128)=l, [128:192)=l2
__global__ void k_split3c(const float* __restrict__ U, __nv_bfloat16* __restrict__ Ucat, int n){
    int i = blockIdx.x*blockDim.x + threadIdx.x;
    if (i >= n) return;
    int r = i >> 6, c = i & 63;
    float v = U[i];
    __nv_bfloat16 a = __float2bfloat16(v);
    float res = v - __bfloat162float(a);
    __nv_bfloat16 b = __float2bfloat16(res);
    float r2 = res - __bfloat162float(b);
    __nv_bfloat16* row = Ucat + (size_t)r*192;
    row[c] = a; row[64 + c] = b; row[128 + c] = __float2bfloat16(r2);
}

// ---------------- augment operand gathers (diag folded in) ----------------

__global__ void k_gather_rows(const float* __restrict__ A, int n, const int* __restrict__ perm,
                              float* Gr, int k){
    size_t t = (size_t)blockIdx.x*blockDim.x + threadIdx.x;
    size_t tot = (size_t)k*(n/4);
    if (t >= tot) return;
    int r = (int)(t / (n/4));
    int c4 = (int)(t % (n/4))*4;
    int pr = perm[r];
    float4 v = *reinterpret_cast<const float4*>(&A[(size_t)pr*n + c4]);
    if (pr >= c4 && pr < c4 + 4) (&v.x)[pr - c4] += 1.0f;
    *reinterpret_cast<float4*>(&Gr[(size_t)r*n + c4]) = v;
}
__global__ void k_gather_cols(const float* __restrict__ A, int n, const int* __restrict__ perm,
                              float* Gc, int k){
    size_t t = (size_t)blockIdx.x*blockDim.x + threadIdx.x;
    if (t >= (size_t)n*k) return;
    int j = (int)(t / k), c = (int)(t % k);
    int pc = perm[c];
    Gc[t] = A[(size_t)j*n + pc] + ((j == pc) ? 1.f : 0.f);
}
__global__ void k_gather_rows_bf(const float* __restrict__ A, int n, const int* __restrict__ perm,
                                 __nv_bfloat16* Gr, int k){
    size_t t = (size_t)blockIdx.x*blockDim.x + threadIdx.x;
    if (t >= (size_t)k*n) return;
    int r = (int)(t / n), c = (int)(t % n);
    int pr = perm[r];
    float v = A[(size_t)pr*n + c] + ((c == pr) ? 1.f : 0.f);
    Gr[t] = __float2bfloat16(v);
}
__global__ void k_gather_cols_bf(const float* __restrict__ A, int n, const int* __restrict__ perm,
                                 __nv_bfloat16* Gc, int k){
    size_t t = (size_t)blockIdx.x*blockDim.x + threadIdx.x;
    if (t >= (size_t)n*k) return;
    int j = (int)(t / k), c = (int)(t % k);
    int pc = perm[c];
    float v = A[(size_t)j*n + pc] + ((j == pc) ? 1.f : 0.f);
    Gc[t] = __float2bfloat16(v);
}

// ---------------- gcn epilogue (sparse path) ----------------

__global__ void k_gcn_epi(const float* Z, const float* U, const float* dinv, const float* fill,
                          const float* __restrict__ b, float* out, int n, int F, int relu){
    int idx = blockIdx.x*blockDim.x + threadIdx.x;
    if (idx >= n*F) return;
    int i = idx / F, f = idx % F;
    float v = dinv[i]*(Z[idx] + fill[i]*U[idx]) + b[f];
    if (relu) v = fmaxf(v, 0.f);
    out[idx] = v;
}

// ---------------- topk / unpool / misc ----------------

// fused ||w|| + score (each block recomputes the tiny norm)
__global__ void k_score(const float* __restrict__ x, int n, int F,
                        const float* __restrict__ w, float* score){
    __shared__ float ws[256];
    __shared__ float sh[256];
    int tid = threadIdx.x;
    float wv = (tid < F) ? w[tid] : 0.f;
    ws[tid] = wv;
    sh[tid] = wv*wv;
    __syncthreads();
    for (int o = 128; o; o >>= 1){
        if (tid < o) sh[tid] += sh[tid + o];
        __syncthreads();
    }
    float inv_nrm = 1.0f / sqrtf(sh[0]);
    int i = blockIdx.x*256 + tid;
    if (i >= n) return;
    const float* r = x + (size_t)i*F;
    float s = 0.f;
    for (int f = 0; f < F; f++) s += r[f]*ws[f];
    score[i] = tanhf(s * inv_nrm);
}

// partial rank counts written to per-chunk slots (no pre-zero, no atomics)
__global__ void k_topk_cnt(const float* __restrict__ s, int n, int* tcnt){
    __shared__ float sj[256];
    int i = blockIdx.x*256 + threadIdx.x;
    float si = s[i];
    int chunk = n / gridDim.y;
    int j0 = blockIdx.y * chunk;
    int c = 0;
    for (int jb = j0; jb < j0 + chunk; jb += 256){
        sj[threadIdx.x] = s[jb + threadIdx.x];
        __syncthreads();
        #pragma unroll 8
        for (int t = 0; t < 256; t++){
            float v = sj[t]; int j = jb + t;
            c += (v > si) || (v == si && j < i);
        }
        __syncthreads();
    }
    tcnt[blockIdx.y*n + i] = c;
}

// fused: sum partial ranks + place perm + inverse perm + gathered/scaled features
__global__ void k_topk_fin(const float* __restrict__ s, const int* __restrict__ tcnt, int chy,
                           const float* __restrict__ x, int F, int n, int k,
                           int* perm, int* inv, float* xg){
    int node = (blockIdx.x*blockDim.x + threadIdx.x) >> 5;
    int lane = threadIdx.x & 31;
    if (node >= n) return;
    int c = 0;
    for (int y = 0; y < chy; y++) c += tcnt[y*n + node];
    bool keep = c < k;
    if (lane == 0){
        if (keep) perm[c] = node;
        inv[node] = keep ? c : -1;
    }
    if (!keep) return;
    float sv = s[node];
    const float* xr = x + (size_t)node*F;
    float* o = xg + (size_t)c*F;
    for (int f = lane; f < F; f += 32) o[f] = xr[f]*sv;
}

// fused unpool: out[i][f] = f<C ? res[i][f] : (inv[i]>=0 ? xprev[inv[i]][f-C] : 0)
__global__ void k_unpool(const float* __restrict__ res, int C,
                         const float* __restrict__ xprev, int Fx,
                         const int* __restrict__ inv, float* out, int n){
    int t = blockIdx.x*blockDim.x + threadIdx.x;
    int W = 2*C;
    if (t >= n*W) return;
    int r = t / W, f = t % W;
    float v;
    if (f < C) v = res[(size_t)r*C + f];
    else {
        int j = inv[r];
        v = (j >= 0) ? xprev[(size_t)j*Fx + (f - C)] : 0.f;
    }
    out[t] = v;
}

__global__ void k_softmax(const float* z, float* out, int n, int C){
    int i = blockIdx.x*blockDim.x + threadIdx.x;
    if (i >= n) return;
    const float* r = z + (size_t)i*C;
    float m = -1e30f;
    for (int c = 0; c < C; c++) m = fmaxf(m, r[c]);
    float s = 0.f;
    for (int c = 0; c < C; c++) s += expf(r[c] - m);
    float inv = 1.0f/s;
    for (int c = 0; c < C; c++) out[(size_t)i*C + c] = expf(r[c] - m)*inv;
}

// ---------------- host orchestration ----------------

extern "C" void kernel_launch(void* const* d_in, const int* in_sizes, int n_in,
                              void* d_out, int out_size){
    const float* x_in = (const float*)d_in[0];
    const int*   eidx = (const int*)d_in[1];
    const float *Wd[5], *bd[5], *pv[4], *Wu[4], *bu[4];
    for (int i = 0; i < 5; i++){ Wd[i] = (const float*)d_in[2 + 2*i]; bd[i] = (const float*)d_in[3 + 2*i]; }
    for (int i = 0; i < 4; i++)  pv[i] = (const float*)d_in[12 + i];
    for (int i = 0; i < 4; i++){ Wu[i] = (const float*)d_in[16 + 2*i]; bu[i] = (const float*)d_in[17 + 2*i]; }
    const float* Wo = (const float*)d_in[24];
    const float* bo = (const float*)d_in[25];
    int E = in_sizes[1] / 2;

    float *pS,*pAs1,*pAs2,*pAs3,*pA4;
    float *px0,*px1,*px2,*px3,*px4,*pxg,*pxu,*pxcat,*pU,*pZ;
    float *pscore;
    float *pdinv[5], *pfill[5];
    __nv_bfloat16 *pUcat;
    int *pperm[4],*pinvl[4],*piz,*ptcnt,*pbucket;
    cudaGetSymbolAddress((void**)&pS,    g_S);
    cudaGetSymbolAddress((void**)&pAs1,  g_As1);
    cudaGetSymbolAddress((void**)&pAs2,  g_As2);
    cudaGetSymbolAddress((void**)&pAs3,  g_As3);
    cudaGetSymbolAddress((void**)&pA4,   g_A4);
    cudaGetSymbolAddress((void**)&px0,   g_x0);
    cudaGetSymbolAddress((void**)&px1,   g_x1);
    cudaGetSymbolAddress((void**)&px2,   g_x2);
    cudaGetSymbolAddress((void**)&px3,   g_x3);
    cudaGetSymbolAddress((void**)&px4,   g_x4);
    cudaGetSymbolAddress((void**)&pxg,   g_xg);
    cudaGetSymbolAddress((void**)&pxu,   g_xu);
    cudaGetSymbolAddress((void**)&pxcat, g_xcat);
    cudaGetSymbolAddress((void**)&pU,    g_bU);
    cudaGetSymbolAddress((void**)&pZ,    g_bZ);
    cudaGetSymbolAddress((void**)&pUcat, g_Ucat);
    cudaGetSymbolAddress((void**)&pdinv[0], g_dinv0); cudaGetSymbolAddress((void**)&pfill[0], g_fill0);
    cudaGetSymbolAddress((void**)&pdinv[1], g_dinv1); cudaGetSymbolAddress((void**)&pfill[1], g_fill1);
    cudaGetSymbolAddress((void**)&pdinv[2], g_dinv2); cudaGetSymbolAddress((void**)&pfill[2], g_fill2);
    cudaGetSymbolAddress((void**)&pdinv[3], g_dinv3); cudaGetSymbolAddress((void**)&pfill[3], g_fill3);
    cudaGetSymbolAddress((void**)&pdinv[4], g_dinv4); cudaGetSymbolAddress((void**)&pfill[4], g_fill4);
    cudaGetSymbolAddress((void**)&pscore, g_score);
    cudaGetSymbolAddress((void**)&pperm[0], g_perm0);
    cudaGetSymbolAddress((void**)&pperm[1], g_perm1);
    cudaGetSymbolAddress((void**)&pperm[2], g_perm2);
    cudaGetSymbolAddress((void**)&pperm[3], g_perm3);
    cudaGetSymbolAddress((void**)&pinvl[0], g_inv0);
    cudaGetSymbolAddress((void**)&pinvl[1], g_inv1);
    cudaGetSymbolAddress((void**)&pinvl[2], g_inv2);
    cudaGetSymbolAddress((void**)&pinvl[3], g_inv3);
    cudaGetSymbolAddress((void**)&piz,    g_iz);
    cudaGetSymbolAddress((void**)&ptcnt,  g_tcnt);
    cudaGetSymbolAddress((void**)&pbucket,g_bucket);
    int* pdegi  = piz;
    int* pselfc = piz + 4096;
    int* pcnt   = piz + 8192;

    char* base = (char*)pS;
    float* pGr   = pS;
    float* pGc   = pS + 4194304;
    float* ppart = pS + 8388608;
    __nv_bfloat16* pA1b = (__nv_bfloat16*)(base + (size_t)48*1024*1024);
    __nv_bfloat16* pGrb = (__nv_bfloat16*)(base + (size_t)56*1024*1024);
    __nv_bfloat16* pGcb = (__nv_bfloat16*)(base + (size_t)60*1024*1024);

    auto g64 = [&](const float* A, const float* B, int M, int N, int K, int SK){
        dim3 g(N/64, M/64, SK);
        k_gemm_f4<64,64,8,8><<<g,64>>>(A,B,ppart,M,N,K,K/SK);
    };
    auto red = [&](float* out, int SK, int M, int N, int flags,
                   const float* dv, const float* fl, const float* bias, const float* Uin){
        size_t tot = (size_t)M*N;
        k_redepi<<<(unsigned)((tot + 255)/256), 256>>>(out, ppart, SK, M, N, flags, dv, fl, bias, Uin);
    };
    auto topk = [&](const float* x, int n, int F, const float* w, int k, int lvl, float* xg){
        k_score<<<(n + 255)/256, 256>>>(x, n, F, w, pscore);
        int chy = n/256 < 8 ? n/256 : 8;
        dim3 gr(n/256, chy);
        k_topk_cnt<<<gr, 256>>>(pscore, n, ptcnt);
        k_topk_fin<<<(n*32 + 255)/256, 256>>>(pscore, ptcnt, chy, x, F, n, k, pperm[lvl], pinvl[lvl], xg);
    };
    auto gcnD = [&](const float* A, int n, const float* dv, const float* fl,
                    const float* x, int fin, const float* W, const float* b,
                    int fout, float* out, bool relu){
        if (fout <= 64 && fin <= 128){
            k_xw2<<<n/16, 256>>>(x, W, pU, n, fout, fin, dv);
        } else {
            g64(x, W, n, fout, fin, 4);
            red(pU, 4, n, fout, 8, dv, nullptr, nullptr, nullptr);
        }
        g64(A, pU, n, fout, n, 16);
        red(out, 16, n, fout, 16 | (relu ? 32 : 0), dv, fl, b, pU);
    };
    // level-1 GCN via bf16 TC: As1 exact bf16, U 3-split concatenated (fp32-exact), one wmma
    auto gcnTC1 = [&](const float* x, int fin, const float* W, const float* b,
                      float* out, bool relu){
        k_xw2<<<2048/16, 256>>>(x, W, pU, 2048, 64, fin, pdinv[1]);
        k_split3c<<<(2048*64 + 255)/256, 256>>>(pU, pUcat, 2048*64);
        const int SK = 8;
        dim3 g(3, 2048/64, SK);
        k_wmma<<<g,128>>>(pA1b, pUcat, ppart, 2048, 192, 2048, 2048/SK);
        k_red3<<<(2048*64 + 255)/256, 256>>>(out, ppart, SK, 2048, pdinv[1], pfill[1], b, pU, relu ? 1 : 0);
    };
    auto gcn0 = [&](const float* x, int fin, const float* W, const float* b,
                    int fout, float* out, bool relu){
        k_xw2<<<4096/16, 256>>>(x, W, pU, 4096, fout, fin, pdinv[0]);
        cudaMemsetAsync(pZ, 0, (size_t)4096*fout*sizeof(float), 0);
        k_spmm<<<(E*32 + 255)/256, 256>>>(eidx, E, pU, pZ, fout);
        int tot = 4096*fout;
        k_gcn_epi<<<(tot + 255)/256, 256>>>(pZ, pU, pdinv[0], pfill[0], b, out, 4096, fout, relu ? 1 : 0);
    };
    auto aug = [&](const float* Asrc, int n, const int* perm, int k, float* Adst){
        size_t rt = (size_t)k*(n/4);
        k_gather_rows<<<(unsigned)((rt + 255)/256), 256>>>(Asrc, n, perm, pGr, k);
        size_t ct = (size_t)n*k;
        k_gather_cols<<<(unsigned)((ct + 255)/256), 256>>>(Asrc, n, perm, pGc, k);
        int SK = (k >= 512) ? 4 : 8;
        g64(pGr, pGc, k, k, n, SK);
        red(Adst, SK, k, k, 4, nullptr, nullptr, nullptr, nullptr);
    };

    // ---- level-0 degrees + buckets ----
    cudaMemsetAsync(piz, 0, 3*4096*sizeof(int), 0);
    k_edge_stats<<<(E + 255)/256, 256>>>(eidx, E, pdegi, pselfc);
    k_deg0_fin<<<(4096 + 255)/256, 256>>>(pdegi, pselfc, pdinv[0], pfill[0], 4096);
    k_bucket_fill<<<(E + 255)/256, 256>>>(eidx, E, pcnt, pbucket);

    // ---- down level 0 (sparse) ----
    gcn0(x_in, 128, Wd[0], bd[0], 32, px0, true);

    // ---- pool to 2048; build As1 via sparse join; deg + bf16 fused ----
    topk(px0, 4096, 32, pv[0], 2048, 0, pxg);
    cudaMemsetAsync(pAs1, 0, (size_t)2048*2048*sizeof(float), 0);
    k_scatter_aug_inv<<<(E + 255)/256, 256>>>(eidx, E, pinvl[0], pAs1, 2048);
    k_join_inv<<<(E + 255)/256, 256>>>(eidx, E, pcnt, pbucket, pinvl[0], pAs1, 2048);
    k_deg<<<(2048 + 7)/8, 256>>>(pAs1, 2048, pdinv[1], pfill[1], pA1b);
    gcnTC1(pxg, 32, Wd[1], bd[1], px1, true);

    // ---- level 2: pooled augment via bf16 wmma ----
    topk(px1, 2048, 64, pv[1], 1024, 1, pxg);
    {
        size_t rt = (size_t)1024*2048;
        k_gather_rows_bf<<<(unsigned)((rt + 255)/256), 256>>>(pAs1, 2048, pperm[1], pGrb, 1024);
        k_gather_cols_bf<<<(unsigned)((rt + 255)/256), 256>>>(pAs1, 2048, pperm[1], pGcb, 1024);
        dim3 g(1024/64, 1024/64, 2);
        k_wmma<<<g,128>>>(pGrb, pGcb, ppart, 1024, 1024, 2048, 1024);
        red(pAs2, 2, 1024, 1024, 4, nullptr, nullptr, nullptr, nullptr);
    }
    k_deg<<<(1024 + 7)/8, 256>>>(pAs2, 1024, pdinv[2], pfill[2], nullptr);
    gcnD(pAs2, 1024, pdinv[2], pfill[2], pxg, 64, Wd[2], bd[2], 128, px2, true);

    // ---- level 3 ----
    topk(px2, 1024, 128, pv[2], 512, 2, pxg);
    aug(pAs2, 1024, pperm[2], 512, pAs3);
    k_deg<<<(512 + 7)/8, 256>>>(pAs3, 512, pdinv[3], pfill[3], nullptr);
    gcnD(pAs3, 512, pdinv[3], pfill[3], pxg, 128, Wd[3], bd[3], 256, px3, true);

    // ---- level 4 ----
    topk(px3, 512, 256, pv[3], 256, 3, pxg);
    aug(pAs3, 512, pperm[3], 256, pA4);
    k_deg<<<(256 + 7)/8, 256>>>(pA4, 256, pdinv[4], pfill[4], nullptr);
    gcnD(pA4, 256, pdinv[4], pfill[4], pxg, 256, Wd[4], bd[4], 512, px4, true);

    // ---- up path (fused unpool) ----
    k_unpool<<<(512*512 + 255)/256, 256>>>(px3, 256, px4, 512, pinvl[3], pxcat, 512);
    gcnD(pAs3, 512, pdinv[3], pfill[3], pxcat, 512, Wu[0], bu[0], 256, pxu, true);

    k_unpool<<<(1024*256 + 255)/256, 256>>>(px2, 128, pxu, 256, pinvl[2], pxcat, 1024);
    gcnD(pAs2, 1024, pdinv[2], pfill[2], pxcat, 256, Wu[1], bu[1], 128, pxu, true);

    k_unpool<<<(2048*128 + 255)/256, 256>>>(px1, 64, pxu, 128, pinvl[1], pxcat, 2048);
    gcnTC1(pxcat, 128, Wu[2], bu[2], pxu, true);

    k_unpool<<<(4096*64 + 255)/256, 256>>>(px0, 32, pxu, 64, pinvl[0], pxcat, 4096);
    gcn0(pxcat, 64, Wu[3], bu[3], 32, pxu, false);

    // ---- final GCN (sparse) + softmax ----
    gcn0(pxu, 32, Wo, bo, 37, pxcat, false);
    k_softmax<<<(4096 + 255)/256, 256>>>(pxcat, (float*)d_out, 4096, 37);
}